// round 1
// baseline (speedup 1.0000x reference)
#include <cuda_runtime.h>
#include <math.h>

#define TT 2048
#define CC 1024
#define HH 16
#define DD 64
#define BBATCH 2
#define MTOT (BBATCH * TT)   // 4096
#define FFDIM (4 * CC)       // 4096

// -------- scratch (alloc-free) --------
__device__ float g_h1[MTOT * CC];          // LN1 out
__device__ float g_q[BBATCH * HH * TT * DD];
__device__ float g_k[BBATCH * HH * TT * DD];
__device__ float g_v[BBATCH * HH * TT * DD];
__device__ float g_attn[MTOT * CC];        // concat-head attn out
__device__ float g_x1[MTOT * CC];          // x + sa
__device__ float g_h2[MTOT * CC];          // LN2 out
__device__ float g_ff1[MTOT * FFDIM];      // relu(h2@w1+b1)

// ============================================================
// LayerNorm: one block (256 thr) per row of 1024
// ============================================================
__global__ void ln_kernel(const float* __restrict__ x, const float* __restrict__ g,
                          const float* __restrict__ b, float* __restrict__ out) {
    __shared__ float red[8];
    __shared__ float s_mu, s_rstd;
    int row = blockIdx.x;
    int tid = threadIdx.x;
    const float* xr = x + (size_t)row * CC;

    float v0 = xr[tid], v1 = xr[tid + 256], v2 = xr[tid + 512], v3 = xr[tid + 768];
    float s = v0 + v1 + v2 + v3;
    #pragma unroll
    for (int o = 16; o > 0; o >>= 1) s += __shfl_xor_sync(0xffffffffu, s, o);
    if ((tid & 31) == 0) red[tid >> 5] = s;
    __syncthreads();
    if (tid == 0) {
        float t = 0.f;
        #pragma unroll
        for (int i = 0; i < 8; i++) t += red[i];
        s_mu = t * (1.0f / CC);
    }
    __syncthreads();
    float mu = s_mu;
    float d0 = v0 - mu, d1 = v1 - mu, d2 = v2 - mu, d3 = v3 - mu;
    float s2 = d0 * d0 + d1 * d1 + d2 * d2 + d3 * d3;
    #pragma unroll
    for (int o = 16; o > 0; o >>= 1) s2 += __shfl_xor_sync(0xffffffffu, s2, o);
    __syncthreads();  // protect red[] reuse
    if ((tid & 31) == 0) red[tid >> 5] = s2;
    __syncthreads();
    if (tid == 0) {
        float t = 0.f;
        #pragma unroll
        for (int i = 0; i < 8; i++) t += red[i];
        s_rstd = rsqrtf(t * (1.0f / CC) + 1e-5f);
    }
    __syncthreads();
    float rstd = s_rstd;
    float* orow = out + (size_t)row * CC;
    orow[tid]       = d0 * rstd * g[tid]       + b[tid];
    orow[tid + 256] = d1 * rstd * g[tid + 256] + b[tid + 256];
    orow[tid + 512] = d2 * rstd * g[tid + 512] + b[tid + 512];
    orow[tid + 768] = d3 * rstd * g[tid + 768] + b[tid + 768];
}

// ============================================================
// Generic fp32 GEMM: C = A(MxK) @ B(KxN) [+bias][+res][relu]
// BM=BN=64, BK=16, 256 threads, 4x4 per thread
// ============================================================
template <bool RELU>
__global__ void gemm_kernel(const float* __restrict__ A, const float* __restrict__ Bm,
                            const float* __restrict__ bias, const float* __restrict__ res,
                            float* __restrict__ C, int M, int N, int K) {
    __shared__ float As[64][17];
    __shared__ float Bs[16][64];
    int tid = threadIdx.x;
    int tx = tid & 15, ty = tid >> 4;
    int m0 = blockIdx.y << 6, n0 = blockIdx.x << 6;
    float acc[4][4] = {};

    int ar = tid >> 2, ac = (tid & 3) << 2;
    int br = tid >> 4, bc = (tid & 15) << 2;

    for (int k0 = 0; k0 < K; k0 += 16) {
        float4 av = *(const float4*)(A + (size_t)(m0 + ar) * K + k0 + ac);
        As[ar][ac] = av.x; As[ar][ac + 1] = av.y; As[ar][ac + 2] = av.z; As[ar][ac + 3] = av.w;
        *(float4*)&Bs[br][bc] = *(const float4*)(Bm + (size_t)(k0 + br) * N + n0 + bc);
        __syncthreads();
        #pragma unroll
        for (int kk = 0; kk < 16; kk++) {
            float a0 = As[ty * 4 + 0][kk], a1 = As[ty * 4 + 1][kk];
            float a2 = As[ty * 4 + 2][kk], a3 = As[ty * 4 + 3][kk];
            float4 bv = *(float4*)&Bs[kk][tx * 4];
            acc[0][0] += a0 * bv.x; acc[0][1] += a0 * bv.y; acc[0][2] += a0 * bv.z; acc[0][3] += a0 * bv.w;
            acc[1][0] += a1 * bv.x; acc[1][1] += a1 * bv.y; acc[1][2] += a1 * bv.z; acc[1][3] += a1 * bv.w;
            acc[2][0] += a2 * bv.x; acc[2][1] += a2 * bv.y; acc[2][2] += a2 * bv.z; acc[2][3] += a2 * bv.w;
            acc[3][0] += a3 * bv.x; acc[3][1] += a3 * bv.y; acc[3][2] += a3 * bv.z; acc[3][3] += a3 * bv.w;
        }
        __syncthreads();
    }

    float4 bv = {0.f, 0.f, 0.f, 0.f};
    if (bias) bv = *(const float4*)(bias + n0 + tx * 4);
    #pragma unroll
    for (int i = 0; i < 4; i++) {
        int m = m0 + ty * 4 + i;
        float4 o;
        o.x = acc[i][0] + bv.x; o.y = acc[i][1] + bv.y;
        o.z = acc[i][2] + bv.z; o.w = acc[i][3] + bv.w;
        if (res) {
            float4 rv = *(const float4*)(res + (size_t)m * N + n0 + tx * 4);
            o.x += rv.x; o.y += rv.y; o.z += rv.z; o.w += rv.w;
        }
        if (RELU) {
            o.x = fmaxf(o.x, 0.f); o.y = fmaxf(o.y, 0.f);
            o.z = fmaxf(o.z, 0.f); o.w = fmaxf(o.w, 0.f);
        }
        *(float4*)(C + (size_t)m * N + n0 + tx * 4) = o;
    }
}

// ============================================================
// QKV GEMM: grid.y encodes (which in {q,k,v}, head). N = 64.
// out layout: (b, h, t, d) contiguous
// ============================================================
__global__ void qkv_kernel(const float* __restrict__ h, const float* __restrict__ wq,
                           const float* __restrict__ wk, const float* __restrict__ wv,
                           float* __restrict__ q, float* __restrict__ k, float* __restrict__ v) {
    __shared__ float As[64][17];
    __shared__ float Bs[16][64];
    int which = blockIdx.y / HH;
    int head = blockIdx.y % HH;
    const float* W = (which == 0 ? wq : (which == 1 ? wk : wv)) + (size_t)head * CC * DD;
    float* O = (which == 0 ? q : (which == 1 ? k : v));

    int tid = threadIdx.x;
    int tx = tid & 15, ty = tid >> 4;
    int m0 = blockIdx.x << 6;
    float acc[4][4] = {};

    int ar = tid >> 2, ac = (tid & 3) << 2;
    int br = tid >> 4, bc = (tid & 15) << 2;

    for (int k0 = 0; k0 < CC; k0 += 16) {
        float4 av = *(const float4*)(h + (size_t)(m0 + ar) * CC + k0 + ac);
        As[ar][ac] = av.x; As[ar][ac + 1] = av.y; As[ar][ac + 2] = av.z; As[ar][ac + 3] = av.w;
        *(float4*)&Bs[br][bc] = *(const float4*)(W + (size_t)(k0 + br) * DD + bc);
        __syncthreads();
        #pragma unroll
        for (int kk = 0; kk < 16; kk++) {
            float a0 = As[ty * 4 + 0][kk], a1 = As[ty * 4 + 1][kk];
            float a2 = As[ty * 4 + 2][kk], a3 = As[ty * 4 + 3][kk];
            float4 bv = *(float4*)&Bs[kk][tx * 4];
            acc[0][0] += a0 * bv.x; acc[0][1] += a0 * bv.y; acc[0][2] += a0 * bv.z; acc[0][3] += a0 * bv.w;
            acc[1][0] += a1 * bv.x; acc[1][1] += a1 * bv.y; acc[1][2] += a1 * bv.z; acc[1][3] += a1 * bv.w;
            acc[2][0] += a2 * bv.x; acc[2][1] += a2 * bv.y; acc[2][2] += a2 * bv.z; acc[2][3] += a2 * bv.w;
            acc[3][0] += a3 * bv.x; acc[3][1] += a3 * bv.y; acc[3][2] += a3 * bv.z; acc[3][3] += a3 * bv.w;
        }
        __syncthreads();
    }
    #pragma unroll
    for (int i = 0; i < 4; i++) {
        int m = m0 + ty * 4 + i;
        int bb = m >> 11;       // m / TT
        int t = m & (TT - 1);
        float4 o = {acc[i][0], acc[i][1], acc[i][2], acc[i][3]};
        *(float4*)(O + (((size_t)(bb * HH + head) * TT + t) << 6) + tx * 4) = o;
    }
}

// ============================================================
// Causal flash attention, fp32. Br=64, Bc=32, 256 threads.
// q,k,v layout (b,h,t,d); out layout (b,t,h*64+d). Scale 1/8 folded into Q.
// ============================================================
__global__ void attn_kernel(const float* __restrict__ Q, const float* __restrict__ K,
                            const float* __restrict__ V, float* __restrict__ out) {
    __shared__ float Qs[64][68];
    __shared__ float Ks[32][68];
    __shared__ float Vs[32][68];
    __shared__ float Ss[64][36];
    __shared__ float row_m[64], row_l[64], row_scale[64];

    int bh = blockIdx.y;            // b*HH + h
    int t0 = blockIdx.x << 6;
    const float* Qp = Q + (size_t)bh * TT * DD;
    const float* Kp = K + (size_t)bh * TT * DD;
    const float* Vp = V + (size_t)bh * TT * DD;
    int tid = threadIdx.x;
    int tx = tid & 15, ty = tid >> 4;   // O map: rows ty*4+i, cols tx*4+j
    int sx = tid & 15, sy = tid >> 4;   // S map: rows sy*4+i, cols sx*2+j

    // load Q tile (scaled)
    for (int i = tid; i < 64 * 16; i += 256) {
        int r = i >> 4, c = (i & 15) << 2;
        float4 qv = *(const float4*)(Qp + (size_t)(t0 + r) * DD + c);
        Qs[r][c] = qv.x * 0.125f; Qs[r][c + 1] = qv.y * 0.125f;
        Qs[r][c + 2] = qv.z * 0.125f; Qs[r][c + 3] = qv.w * 0.125f;
    }
    if (tid < 64) { row_m[tid] = -INFINITY; row_l[tid] = 0.f; }
    float acc[4][4] = {};
    __syncthreads();

    for (int s0 = 0; s0 < t0 + 64; s0 += 32) {
        // load K,V tiles (32x64)
        for (int i = tid; i < 32 * 16; i += 256) {
            int r = i >> 4, c = (i & 15) << 2;
            *(float4*)&Ks[r][c] = *(const float4*)(Kp + (size_t)(s0 + r) * DD + c);
            *(float4*)&Vs[r][c] = *(const float4*)(Vp + (size_t)(s0 + r) * DD + c);
        }
        __syncthreads();

        // S = Q @ K^T : each thread 4 rows x 2 cols
        float sacc[4][2] = {};
        #pragma unroll
        for (int d = 0; d < 64; d += 4) {
            float4 qv[4], kv[2];
            #pragma unroll
            for (int i = 0; i < 4; i++) qv[i] = *(float4*)&Qs[sy * 4 + i][d];
            #pragma unroll
            for (int j = 0; j < 2; j++) kv[j] = *(float4*)&Ks[sx * 2 + j][d];
            #pragma unroll
            for (int i = 0; i < 4; i++)
                #pragma unroll
                for (int j = 0; j < 2; j++)
                    sacc[i][j] += qv[i].x * kv[j].x + qv[i].y * kv[j].y +
                                  qv[i].z * kv[j].z + qv[i].w * kv[j].w;
        }
        #pragma unroll
        for (int i = 0; i < 4; i++)
            #pragma unroll
            for (int j = 0; j < 2; j++)
                Ss[sy * 4 + i][sx * 2 + j] = sacc[i][j];
        __syncthreads();

        // online softmax per row (threads 0..63)
        if (tid < 64) {
            int t = t0 + tid;
            int lim = t - s0 + 1;            // valid cols: c < lim
            if (lim > 32) lim = 32;
            float m_old = row_m[tid];
            float lsum = row_l[tid];
            float sc = 1.f;
            if (lim > 0) {
                float mx = m_old;
                for (int c = 0; c < lim; c++) mx = fmaxf(mx, Ss[tid][c]);
                sc = __expf(m_old - mx);     // exp(-inf)=0 on first tile
                lsum *= sc;
                #pragma unroll
                for (int c = 0; c < 32; c++) {
                    float p = (c < lim) ? __expf(Ss[tid][c] - mx) : 0.f;
                    Ss[tid][c] = p;
                    lsum += p;
                }
                row_m[tid] = mx;
                row_l[tid] = lsum;
            } else {
                #pragma unroll
                for (int c = 0; c < 32; c++) Ss[tid][c] = 0.f;
            }
            row_scale[tid] = sc;
        }
        __syncthreads();

        // O = O*scale + P @ V
        #pragma unroll
        for (int i = 0; i < 4; i++) {
            float sc = row_scale[ty * 4 + i];
            acc[i][0] *= sc; acc[i][1] *= sc; acc[i][2] *= sc; acc[i][3] *= sc;
        }
        #pragma unroll
        for (int s = 0; s < 32; s++) {
            float4 vv = *(float4*)&Vs[s][tx * 4];
            #pragma unroll
            for (int i = 0; i < 4; i++) {
                float p = Ss[ty * 4 + i][s];
                acc[i][0] += p * vv.x; acc[i][1] += p * vv.y;
                acc[i][2] += p * vv.z; acc[i][3] += p * vv.w;
            }
        }
        __syncthreads();
    }

    int b = bh >> 4, h = bh & 15;
    #pragma unroll
    for (int i = 0; i < 4; i++) {
        int t = t0 + ty * 4 + i;
        float inv = 1.f / row_l[ty * 4 + i];
        float4 o = {acc[i][0] * inv, acc[i][1] * inv, acc[i][2] * inv, acc[i][3] * inv};
        *(float4*)(out + ((size_t)(b * TT + t)) * CC + h * DD + tx * 4) = o;
    }
}

// ============================================================
// launch
// ============================================================
extern "C" void kernel_launch(void* const* d_in, const int* in_sizes, int n_in,
                              void* d_out, int out_size) {
    const float* x      = (const float*)d_in[0];
    const float* wq     = (const float*)d_in[1];
    const float* wk     = (const float*)d_in[2];
    const float* wv     = (const float*)d_in[3];
    const float* w_proj = (const float*)d_in[4];
    const float* b_proj = (const float*)d_in[5];
    const float* w1     = (const float*)d_in[6];
    const float* b1     = (const float*)d_in[7];
    const float* w2     = (const float*)d_in[8];
    const float* b2     = (const float*)d_in[9];
    const float* g1     = (const float*)d_in[10];
    const float* be1    = (const float*)d_in[11];
    const float* g2     = (const float*)d_in[12];
    const float* be2    = (const float*)d_in[13];
    float* out = (float*)d_out;

    float *h1, *q, *k, *v, *attn, *x1, *h2, *ff1;
    cudaGetSymbolAddress((void**)&h1, g_h1);
    cudaGetSymbolAddress((void**)&q, g_q);
    cudaGetSymbolAddress((void**)&k, g_k);
    cudaGetSymbolAddress((void**)&v, g_v);
    cudaGetSymbolAddress((void**)&attn, g_attn);
    cudaGetSymbolAddress((void**)&x1, g_x1);
    cudaGetSymbolAddress((void**)&h2, g_h2);
    cudaGetSymbolAddress((void**)&ff1, g_ff1);

    // 1. LN1
    ln_kernel<<<MTOT, 256>>>(x, g1, be1, h1);
    // 2. QKV
    qkv_kernel<<<dim3(MTOT / 64, 3 * HH), 256>>>(h1, wq, wk, wv, q, k, v);
    // 3. attention
    attn_kernel<<<dim3(TT / 64, BBATCH * HH), 256>>>(q, k, v, attn);
    // 4. proj + bias + residual -> x1
    gemm_kernel<false><<<dim3(CC / 64, MTOT / 64), 256>>>(attn, w_proj, b_proj, x, x1,
                                                          MTOT, CC, CC);
    // 5. LN2
    ln_kernel<<<MTOT, 256>>>(x1, g2, be2, h2);
    // 6. FF1 + bias + relu
    gemm_kernel<true><<<dim3(FFDIM / 64, MTOT / 64), 256>>>(h2, w1, b1, nullptr, ff1,
                                                            MTOT, FFDIM, CC);
    // 7. FF2 + bias + residual -> out
    gemm_kernel<false><<<dim3(CC / 64, MTOT / 64), 256>>>(ff1, w2, b2, x1, out,
                                                          MTOT, CC, FFDIM);
}

// round 3
// speedup vs baseline: 3.4597x; 3.4597x over previous
#include <cuda_runtime.h>
#include <math.h>

#define TT 2048
#define CC 1024
#define HH 16
#define DD 64
#define BBATCH 2
#define MTOT (BBATCH * TT)   // 4096
#define FFDIM (4 * CC)       // 4096

// -------- scratch (alloc-free) --------
__device__ float g_h1[MTOT * CC];
__device__ float g_q[MTOT * CC];     // (b,h,t,d)
__device__ float g_k[MTOT * CC];
__device__ float g_v[MTOT * CC];
__device__ float g_attn[MTOT * CC];
__device__ float g_x1[MTOT * CC];
__device__ float g_h2[MTOT * CC];
__device__ float g_ff1[MTOT * FFDIM];

// -------- tf32 helpers --------
__device__ __forceinline__ unsigned f2tf(float f) {
    unsigned u;
    asm("cvt.rna.tf32.f32 %0, %1;" : "=r"(u) : "f"(f));
    return u;
}
__device__ __forceinline__ void mma_tf32(float* c, const unsigned* a, const unsigned* b) {
    asm volatile(
        "mma.sync.aligned.m16n8k8.row.col.f32.tf32.tf32.f32 "
        "{%0,%1,%2,%3}, {%4,%5,%6,%7}, {%8,%9}, {%0,%1,%2,%3};"
        : "+f"(c[0]), "+f"(c[1]), "+f"(c[2]), "+f"(c[3])
        : "r"(a[0]), "r"(a[1]), "r"(a[2]), "r"(a[3]), "r"(b[0]), "r"(b[1]));
}

// ============================================================
// LayerNorm: one block (256 thr) per row of 1024
// ============================================================
__global__ void ln_kernel(const float* __restrict__ x, const float* __restrict__ g,
                          const float* __restrict__ b, float* __restrict__ out) {
    __shared__ float red[8];
    __shared__ float s_mu, s_rstd;
    int row = blockIdx.x;
    int tid = threadIdx.x;
    const float* xr = x + (size_t)row * CC;

    float v0 = xr[tid], v1 = xr[tid + 256], v2 = xr[tid + 512], v3 = xr[tid + 768];
    float s = v0 + v1 + v2 + v3;
    #pragma unroll
    for (int o = 16; o > 0; o >>= 1) s += __shfl_xor_sync(0xffffffffu, s, o);
    if ((tid & 31) == 0) red[tid >> 5] = s;
    __syncthreads();
    if (tid == 0) {
        float t = 0.f;
        #pragma unroll
        for (int i = 0; i < 8; i++) t += red[i];
        s_mu = t * (1.0f / CC);
    }
    __syncthreads();
    float mu = s_mu;
    float d0 = v0 - mu, d1 = v1 - mu, d2 = v2 - mu, d3 = v3 - mu;
    float s2 = d0 * d0 + d1 * d1 + d2 * d2 + d3 * d3;
    #pragma unroll
    for (int o = 16; o > 0; o >>= 1) s2 += __shfl_xor_sync(0xffffffffu, s2, o);
    __syncthreads();
    if ((tid & 31) == 0) red[tid >> 5] = s2;
    __syncthreads();
    if (tid == 0) {
        float t = 0.f;
        #pragma unroll
        for (int i = 0; i < 8; i++) t += red[i];
        s_rstd = rsqrtf(t * (1.0f / CC) + 1e-5f);
    }
    __syncthreads();
    float rstd = s_rstd;
    float* orow = out + (size_t)row * CC;
    orow[tid]       = d0 * rstd * g[tid]       + b[tid];
    orow[tid + 256] = d1 * rstd * g[tid + 256] + b[tid + 256];
    orow[tid + 512] = d2 * rstd * g[tid + 512] + b[tid + 512];
    orow[tid + 768] = d3 * rstd * g[tid + 768] + b[tid + 768];
}

// ============================================================
// Generic tf32 tensor-core GEMM: C = A(MxK) @ B(KxN) [+bias][+res][relu]
// BM=128, BN=128, BK=32, 256 threads = 8 warps (2x4), warp tile 64x32
// ============================================================
template <bool RELU>
__global__ __launch_bounds__(256) void gemm_mma(
    const float* __restrict__ A, const float* __restrict__ Bm,
    const float* __restrict__ bias, const float* __restrict__ res,
    float* __restrict__ C, int M, int N, int K) {
    __shared__ unsigned As[128][36];   // pad 36 -> frag LDS conflict-free
    __shared__ unsigned Bs[32][132];   // pad +4
    int tid = threadIdx.x;
    int warp = tid >> 5, lane = tid & 31;
    int g = lane >> 2, tig = lane & 3;
    int wm = (warp >> 2) * 64, wn = (warp & 3) * 32;
    int m0 = blockIdx.y * 128, n0 = blockIdx.x * 128;

    float acc[4][4][4] = {};

    for (int k0 = 0; k0 < K; k0 += 32) {
        #pragma unroll
        for (int i = 0; i < 4; i++) {
            int s = tid + 256 * i;
            int r = s >> 3, c = (s & 7) * 4;
            float4 v = *(const float4*)(A + (size_t)(m0 + r) * K + k0 + c);
            As[r][c] = f2tf(v.x); As[r][c + 1] = f2tf(v.y);
            As[r][c + 2] = f2tf(v.z); As[r][c + 3] = f2tf(v.w);
        }
        #pragma unroll
        for (int i = 0; i < 4; i++) {
            int s = tid + 256 * i;
            int r = s >> 5, c = (s & 31) * 4;
            float4 v = *(const float4*)(Bm + (size_t)(k0 + r) * N + n0 + c);
            Bs[r][c] = f2tf(v.x); Bs[r][c + 1] = f2tf(v.y);
            Bs[r][c + 2] = f2tf(v.z); Bs[r][c + 3] = f2tf(v.w);
        }
        __syncthreads();
        #pragma unroll
        for (int ks = 0; ks < 4; ks++) {
            unsigned af[4][4], bf[4][2];
            #pragma unroll
            for (int mi = 0; mi < 4; mi++) {
                int r = wm + mi * 16 + g;
                af[mi][0] = As[r][ks * 8 + tig];
                af[mi][1] = As[r + 8][ks * 8 + tig];
                af[mi][2] = As[r][ks * 8 + tig + 4];
                af[mi][3] = As[r + 8][ks * 8 + tig + 4];
            }
            #pragma unroll
            for (int nj = 0; nj < 4; nj++) {
                bf[nj][0] = Bs[ks * 8 + tig][wn + nj * 8 + g];
                bf[nj][1] = Bs[ks * 8 + tig + 4][wn + nj * 8 + g];
            }
            #pragma unroll
            for (int mi = 0; mi < 4; mi++)
                #pragma unroll
                for (int nj = 0; nj < 4; nj++)
                    mma_tf32(acc[mi][nj], af[mi], bf[nj]);
        }
        __syncthreads();
    }

    #pragma unroll
    for (int mi = 0; mi < 4; mi++) {
        #pragma unroll
        for (int nj = 0; nj < 4; nj++) {
            int c = n0 + wn + nj * 8 + 2 * tig;
            int r0 = m0 + wm + mi * 16 + g;
            int r1 = r0 + 8;
            float2 o0 = {acc[mi][nj][0], acc[mi][nj][1]};
            float2 o1 = {acc[mi][nj][2], acc[mi][nj][3]};
            if (bias) {
                float2 bv = *(const float2*)(bias + c);
                o0.x += bv.x; o0.y += bv.y; o1.x += bv.x; o1.y += bv.y;
            }
            if (res) {
                float2 ra = *(const float2*)(res + (size_t)r0 * N + c);
                float2 rb = *(const float2*)(res + (size_t)r1 * N + c);
                o0.x += ra.x; o0.y += ra.y; o1.x += rb.x; o1.y += rb.y;
            }
            if (RELU) {
                o0.x = fmaxf(o0.x, 0.f); o0.y = fmaxf(o0.y, 0.f);
                o1.x = fmaxf(o1.x, 0.f); o1.y = fmaxf(o1.y, 0.f);
            }
            *(float2*)(C + (size_t)r0 * N + c) = o0;
            *(float2*)(C + (size_t)r1 * N + c) = o1;
        }
    }
}

// ============================================================
// QKV GEMM (tensor core): grid.y = which*16 + head, N=64 per block.
// BM=128, BK=32, 128 threads = 4 warps (2x2), warp tile 64x32.
// out layout (b,h,t,d)
// ============================================================
__global__ __launch_bounds__(128) void qkv_mma(
    const float* __restrict__ h, const float* __restrict__ wq,
    const float* __restrict__ wk, const float* __restrict__ wv,
    float* __restrict__ q, float* __restrict__ k, float* __restrict__ v) {
    __shared__ unsigned As[128][36];
    __shared__ unsigned Bs[32][68];
    int which = blockIdx.y / HH, head = blockIdx.y % HH;
    const float* W = (which == 0 ? wq : (which == 1 ? wk : wv)) + (size_t)head * CC * DD;
    float* O = (which == 0 ? q : (which == 1 ? k : v));
    int tid = threadIdx.x;
    int warp = tid >> 5, lane = tid & 31;
    int g = lane >> 2, tig = lane & 3;
    int wm = (warp >> 1) * 64, wn = (warp & 1) * 32;
    int m0 = blockIdx.x * 128;

    float acc[4][4][4] = {};

    for (int k0 = 0; k0 < CC; k0 += 32) {
        #pragma unroll
        for (int i = 0; i < 8; i++) {
            int s = tid + 128 * i;
            int r = s >> 3, c = (s & 7) * 4;
            float4 vv = *(const float4*)(h + (size_t)(m0 + r) * CC + k0 + c);
            As[r][c] = f2tf(vv.x); As[r][c + 1] = f2tf(vv.y);
            As[r][c + 2] = f2tf(vv.z); As[r][c + 3] = f2tf(vv.w);
        }
        #pragma unroll
        for (int i = 0; i < 4; i++) {
            int s = tid + 128 * i;
            int r = s >> 4, c = (s & 15) * 4;
            float4 vv = *(const float4*)(W + (size_t)(k0 + r) * DD + c);
            Bs[r][c] = f2tf(vv.x); Bs[r][c + 1] = f2tf(vv.y);
            Bs[r][c + 2] = f2tf(vv.z); Bs[r][c + 3] = f2tf(vv.w);
        }
        __syncthreads();
        #pragma unroll
        for (int ks = 0; ks < 4; ks++) {
            unsigned af[4][4], bf[4][2];
            #pragma unroll
            for (int mi = 0; mi < 4; mi++) {
                int r = wm + mi * 16 + g;
                af[mi][0] = As[r][ks * 8 + tig];
                af[mi][1] = As[r + 8][ks * 8 + tig];
                af[mi][2] = As[r][ks * 8 + tig + 4];
                af[mi][3] = As[r + 8][ks * 8 + tig + 4];
            }
            #pragma unroll
            for (int nj = 0; nj < 4; nj++) {
                bf[nj][0] = Bs[ks * 8 + tig][wn + nj * 8 + g];
                bf[nj][1] = Bs[ks * 8 + tig + 4][wn + nj * 8 + g];
            }
            #pragma unroll
            for (int mi = 0; mi < 4; mi++)
                #pragma unroll
                for (int nj = 0; nj < 4; nj++)
                    mma_tf32(acc[mi][nj], af[mi], bf[nj]);
        }
        __syncthreads();
    }

    #pragma unroll
    for (int mi = 0; mi < 4; mi++) {
        #pragma unroll
        for (int nj = 0; nj < 4; nj++) {
            int c = wn + nj * 8 + 2 * tig;
            int m0r = m0 + wm + mi * 16 + g;
            int m1r = m0r + 8;
            int b0 = m0r >> 11, t0i = m0r & (TT - 1);
            int b1 = m1r >> 11, t1i = m1r & (TT - 1);
            float2 o0 = {acc[mi][nj][0], acc[mi][nj][1]};
            float2 o1 = {acc[mi][nj][2], acc[mi][nj][3]};
            *(float2*)(O + (((size_t)(b0 * HH + head) * TT + t0i) << 6) + c) = o0;
            *(float2*)(O + (((size_t)(b1 * HH + head) * TT + t1i) << 6) + c) = o1;
        }
    }
}

// ============================================================
// Flash attention (tensor core). Br=64, Bc=64, 128 threads (4 warps).
// Q in register A-fragments; K/P share smem; online softmax in regs.
// Scale 1/8 folded into Q. q,k,v (b,h,t,d); out (b,t,h*64+d).
// ============================================================
__global__ __launch_bounds__(128) void attn_mma(
    const float* __restrict__ Q, const float* __restrict__ K,
    const float* __restrict__ V, float* __restrict__ out) {
    __shared__ unsigned Ks[64][68];   // K tile, then reused as P tile
    __shared__ unsigned Vs[64][68];   // V tile (also Q staging at start)

    int bh = blockIdx.y;
    int t0 = blockIdx.x * 64;
    const float* Qp = Q + (size_t)bh * TT * DD;
    const float* Kp = K + (size_t)bh * TT * DD;
    const float* Vp = V + (size_t)bh * TT * DD;
    int tid = threadIdx.x;
    int warp = tid >> 5, lane = tid & 31;
    int g = lane >> 2, tig = lane & 3;
    int wr = warp * 16;   // warp's row base within tile

    // stage Q (scaled, tf32) into Vs, then pull A-fragments into regs
    #pragma unroll
    for (int i = 0; i < 8; i++) {
        int s = tid + 128 * i;
        int r = s >> 4, c = (s & 15) * 4;
        float4 qv = *(const float4*)(Qp + (size_t)(t0 + r) * DD + c);
        Vs[r][c] = f2tf(qv.x * 0.125f); Vs[r][c + 1] = f2tf(qv.y * 0.125f);
        Vs[r][c + 2] = f2tf(qv.z * 0.125f); Vs[r][c + 3] = f2tf(qv.w * 0.125f);
    }
    __syncthreads();
    unsigned qa[8][4];
    #pragma unroll
    for (int ks = 0; ks < 8; ks++) {
        qa[ks][0] = Vs[wr + g][ks * 8 + tig];
        qa[ks][1] = Vs[wr + 8 + g][ks * 8 + tig];
        qa[ks][2] = Vs[wr + g][ks * 8 + tig + 4];
        qa[ks][3] = Vs[wr + 8 + g][ks * 8 + tig + 4];
    }
    __syncthreads();

    float m0r = -1e30f, m1r = -1e30f, l0 = 0.f, l1 = 0.f;
    float oacc[8][4] = {};

    int ntiles = t0 / 64 + 1;
    for (int it = 0; it < ntiles; it++) {
        int s0 = it * 64;
        // load K, V tiles
        #pragma unroll
        for (int i = 0; i < 8; i++) {
            int s = tid + 128 * i;
            int r = s >> 4, c = (s & 15) * 4;
            float4 kv = *(const float4*)(Kp + (size_t)(s0 + r) * DD + c);
            Ks[r][c] = f2tf(kv.x); Ks[r][c + 1] = f2tf(kv.y);
            Ks[r][c + 2] = f2tf(kv.z); Ks[r][c + 3] = f2tf(kv.w);
            float4 vv = *(const float4*)(Vp + (size_t)(s0 + r) * DD + c);
            Vs[r][c] = f2tf(vv.x); Vs[r][c + 1] = f2tf(vv.y);
            Vs[r][c + 2] = f2tf(vv.z); Vs[r][c + 3] = f2tf(vv.w);
        }
        __syncthreads();

        // S = Q @ K^T  (64x64 per CTA, 16x64 per warp)
        float sacc[8][4] = {};
        #pragma unroll
        for (int ks = 0; ks < 8; ks++) {
            #pragma unroll
            for (int nj = 0; nj < 8; nj++) {
                unsigned bf[2];
                bf[0] = Ks[nj * 8 + g][ks * 8 + tig];
                bf[1] = Ks[nj * 8 + g][ks * 8 + tig + 4];
                mma_tf32(sacc[nj], qa[ks], bf);
            }
        }
        __syncthreads();   // all S-mma reads of Ks done before P overwrite

        // causal mask (diagonal tile only)
        if (s0 == t0) {
            #pragma unroll
            for (int nj = 0; nj < 8; nj++) {
                int c0 = nj * 8 + 2 * tig, c1 = c0 + 1;
                int r0 = wr + g, r1 = r0 + 8;
                if (c0 > r0) sacc[nj][0] = -1e30f;
                if (c1 > r0) sacc[nj][1] = -1e30f;
                if (c0 > r1) sacc[nj][2] = -1e30f;
                if (c1 > r1) sacc[nj][3] = -1e30f;
            }
        }

        // online softmax (rows g and g+8 of this warp's 16 rows)
        float mt0 = -1e30f, mt1 = -1e30f;
        #pragma unroll
        for (int nj = 0; nj < 8; nj++) {
            mt0 = fmaxf(mt0, fmaxf(sacc[nj][0], sacc[nj][1]));
            mt1 = fmaxf(mt1, fmaxf(sacc[nj][2], sacc[nj][3]));
        }
        #pragma unroll
        for (int o = 1; o <= 2; o <<= 1) {
            mt0 = fmaxf(mt0, __shfl_xor_sync(0xffffffffu, mt0, o));
            mt1 = fmaxf(mt1, __shfl_xor_sync(0xffffffffu, mt1, o));
        }
        float mn0 = fmaxf(m0r, mt0), mn1 = fmaxf(m1r, mt1);
        float sc0 = __expf(m0r - mn0), sc1 = __expf(m1r - mn1);
        float sum0 = 0.f, sum1 = 0.f;
        #pragma unroll
        for (int nj = 0; nj < 8; nj++) {
            float p00 = __expf(sacc[nj][0] - mn0);
            float p01 = __expf(sacc[nj][1] - mn0);
            float p10 = __expf(sacc[nj][2] - mn1);
            float p11 = __expf(sacc[nj][3] - mn1);
            sum0 += p00 + p01; sum1 += p10 + p11;
            int c = nj * 8 + 2 * tig;
            Ks[wr + g][c] = f2tf(p00); Ks[wr + g][c + 1] = f2tf(p01);
            Ks[wr + 8 + g][c] = f2tf(p10); Ks[wr + 8 + g][c + 1] = f2tf(p11);
        }
        #pragma unroll
        for (int o = 1; o <= 2; o <<= 1) {
            sum0 += __shfl_xor_sync(0xffffffffu, sum0, o);
            sum1 += __shfl_xor_sync(0xffffffffu, sum1, o);
        }
        l0 = l0 * sc0 + sum0;
        l1 = l1 * sc1 + sum1;
        m0r = mn0; m1r = mn1;
        #pragma unroll
        for (int nj = 0; nj < 8; nj++) {
            oacc[nj][0] *= sc0; oacc[nj][1] *= sc0;
            oacc[nj][2] *= sc1; oacc[nj][3] *= sc1;
        }
        __syncthreads();   // P visible to all warps

        // O += P @ V
        #pragma unroll
        for (int ks = 0; ks < 8; ks++) {
            unsigned pa[4];
            pa[0] = Ks[wr + g][ks * 8 + tig];
            pa[1] = Ks[wr + 8 + g][ks * 8 + tig];
            pa[2] = Ks[wr + g][ks * 8 + tig + 4];
            pa[3] = Ks[wr + 8 + g][ks * 8 + tig + 4];
            #pragma unroll
            for (int nj = 0; nj < 8; nj++) {
                unsigned bf[2];
                bf[0] = Vs[ks * 8 + tig][nj * 8 + g];
                bf[1] = Vs[ks * 8 + tig + 4][nj * 8 + g];
                mma_tf32(oacc[nj], pa, bf);
            }
        }
        __syncthreads();   // done with Ks/Vs before next tile load
    }

    float inv0 = 1.f / l0, inv1 = 1.f / l1;
    int b = bh >> 4, hh = bh & 15;
    int tr0 = t0 + wr + g, tr1 = tr0 + 8;
    #pragma unroll
    for (int nj = 0; nj < 8; nj++) {
        int c = hh * DD + nj * 8 + 2 * tig;
        float2 o0 = {oacc[nj][0] * inv0, oacc[nj][1] * inv0};
        float2 o1 = {oacc[nj][2] * inv1, oacc[nj][3] * inv1};
        *(float2*)(out + (size_t)(b * TT + tr0) * CC + c) = o0;
        *(float2*)(out + (size_t)(b * TT + tr1) * CC + c) = o1;
    }
}

// ============================================================
// launch
// ============================================================
extern "C" void kernel_launch(void* const* d_in, const int* in_sizes, int n_in,
                              void* d_out, int out_size) {
    const float* x      = (const float*)d_in[0];
    const float* wq     = (const float*)d_in[1];
    const float* wk     = (const float*)d_in[2];
    const float* wv     = (const float*)d_in[3];
    const float* w_proj = (const float*)d_in[4];
    const float* b_proj = (const float*)d_in[5];
    const float* w1     = (const float*)d_in[6];
    const float* b1     = (const float*)d_in[7];
    const float* w2     = (const float*)d_in[8];
    const float* b2     = (const float*)d_in[9];
    const float* g1     = (const float*)d_in[10];
    const float* be1    = (const float*)d_in[11];
    const float* g2     = (const float*)d_in[12];
    const float* be2    = (const float*)d_in[13];
    float* out = (float*)d_out;

    float *h1, *q, *k, *v, *attn, *x1, *h2, *ff1;
    cudaGetSymbolAddress((void**)&h1, g_h1);
    cudaGetSymbolAddress((void**)&q, g_q);
    cudaGetSymbolAddress((void**)&k, g_k);
    cudaGetSymbolAddress((void**)&v, g_v);
    cudaGetSymbolAddress((void**)&attn, g_attn);
    cudaGetSymbolAddress((void**)&x1, g_x1);
    cudaGetSymbolAddress((void**)&h2, g_h2);
    cudaGetSymbolAddress((void**)&ff1, g_ff1);

    // 1. LN1
    ln_kernel<<<MTOT, 256>>>(x, g1, be1, h1);
    // 2. QKV
    qkv_mma<<<dim3(MTOT / 128, 3 * HH), 128>>>(h1, wq, wk, wv, q, k, v);
    // 3. attention
    attn_mma<<<dim3(TT / 64, BBATCH * HH), 128>>>(q, k, v, attn);
    // 4. proj + bias + residual -> x1
    gemm_mma<false><<<dim3(CC / 128, MTOT / 128), 256>>>(attn, w_proj, b_proj, x, x1,
                                                         MTOT, CC, CC);
    // 5. LN2
    ln_kernel<<<MTOT, 256>>>(x1, g2, be2, h2);
    // 6. FF1 + bias + relu
    gemm_mma<true><<<dim3(FFDIM / 128, MTOT / 128), 256>>>(h2, w1, b1, nullptr, ff1,
                                                           MTOT, FFDIM, CC);
    // 7. FF2 + bias + residual -> out
    gemm_mma<false><<<dim3(CC / 128, MTOT / 128), 256>>>(ff1, w2, b2, x1, out,
                                                         MTOT, CC, FFDIM);
}

// round 4
// speedup vs baseline: 4.1128x; 1.1888x over previous
#include <cuda_runtime.h>
#include <math.h>
#include <stdint.h>

#define TT 2048
#define CC 1024
#define HH 16
#define DD 64
#define BBATCH 2
#define MTOT (BBATCH * TT)   // 4096
#define FFDIM (4 * CC)       // 4096

// -------- scratch (alloc-free) --------
__device__ float g_h1[MTOT * CC];
__device__ float g_q[MTOT * CC];     // (b,h,t,d)
__device__ float g_k[MTOT * CC];
__device__ float g_v[MTOT * CC];
__device__ float g_attn[MTOT * CC];
__device__ float g_x1[MTOT * CC];
__device__ float g_h2[MTOT * CC];
__device__ float g_ff1[MTOT * FFDIM];

// -------- helpers --------
__device__ __forceinline__ unsigned f2tf(float f) {
    unsigned u;
    asm("cvt.rna.tf32.f32 %0, %1;" : "=r"(u) : "f"(f));
    return u;
}
__device__ __forceinline__ void mma_tf32(float* c, const unsigned* a, const unsigned* b) {
    asm volatile(
        "mma.sync.aligned.m16n8k8.row.col.f32.tf32.tf32.f32 "
        "{%0,%1,%2,%3}, {%4,%5,%6,%7}, {%8,%9}, {%0,%1,%2,%3};"
        : "+f"(c[0]), "+f"(c[1]), "+f"(c[2]), "+f"(c[3])
        : "r"(a[0]), "r"(a[1]), "r"(a[2]), "r"(a[3]), "r"(b[0]), "r"(b[1]));
}
__device__ __forceinline__ void cp16(uint32_t s, const void* g) {
    asm volatile("cp.async.ca.shared.global [%0], [%1], 16;" :: "r"(s), "l"(g));
}
__device__ __forceinline__ void cp_commit() { asm volatile("cp.async.commit_group;"); }
template <int N>
__device__ __forceinline__ void cp_wait() { asm volatile("cp.async.wait_group %0;" :: "n"(N)); }
__device__ __forceinline__ void ldsm4(unsigned& r0, unsigned& r1, unsigned& r2, unsigned& r3,
                                      uint32_t a) {
    asm volatile("ldmatrix.sync.aligned.m8n8.x4.shared.b16 {%0,%1,%2,%3}, [%4];"
                 : "=r"(r0), "=r"(r1), "=r"(r2), "=r"(r3) : "r"(a));
}

// ============================================================
// LayerNorm: one block (256 thr) per row of 1024
// ============================================================
__global__ void ln_kernel(const float* __restrict__ x, const float* __restrict__ g,
                          const float* __restrict__ b, float* __restrict__ out) {
    __shared__ float red[8];
    __shared__ float s_mu, s_rstd;
    int row = blockIdx.x;
    int tid = threadIdx.x;
    const float* xr = x + (size_t)row * CC;

    float v0 = xr[tid], v1 = xr[tid + 256], v2 = xr[tid + 512], v3 = xr[tid + 768];
    float s = v0 + v1 + v2 + v3;
    #pragma unroll
    for (int o = 16; o > 0; o >>= 1) s += __shfl_xor_sync(0xffffffffu, s, o);
    if ((tid & 31) == 0) red[tid >> 5] = s;
    __syncthreads();
    if (tid == 0) {
        float t = 0.f;
        #pragma unroll
        for (int i = 0; i < 8; i++) t += red[i];
        s_mu = t * (1.0f / CC);
    }
    __syncthreads();
    float mu = s_mu;
    float d0 = v0 - mu, d1 = v1 - mu, d2 = v2 - mu, d3 = v3 - mu;
    float s2 = d0 * d0 + d1 * d1 + d2 * d2 + d3 * d3;
    #pragma unroll
    for (int o = 16; o > 0; o >>= 1) s2 += __shfl_xor_sync(0xffffffffu, s2, o);
    __syncthreads();
    if ((tid & 31) == 0) red[tid >> 5] = s2;
    __syncthreads();
    if (tid == 0) {
        float t = 0.f;
        #pragma unroll
        for (int i = 0; i < 8; i++) t += red[i];
        s_rstd = rsqrtf(t * (1.0f / CC) + 1e-5f);
    }
    __syncthreads();
    float rstd = s_rstd;
    float* orow = out + (size_t)row * CC;
    orow[tid]       = d0 * rstd * g[tid]       + b[tid];
    orow[tid + 256] = d1 * rstd * g[tid + 256] + b[tid + 256];
    orow[tid + 512] = d2 * rstd * g[tid + 512] + b[tid + 512];
    orow[tid + 768] = d3 * rstd * g[tid + 768] + b[tid + 768];
}

// ============================================================
// tf32 GEMM, cp.async 2-stage, ldmatrix A-frags.
// BM=128, BN=128, BK=32, 256 thr = 8 warps (2x4), warp tile 64x32.
// As pitch 36 (ldmatrix conflict-free), Bs pitch 136 (scalar CF).
// Dynamic smem: 2*(128*36 + 32*136)*4 = 71680 B.
// ============================================================
#define G_ASTG (128 * 36)
#define G_BSTG (32 * 136)
#define G_SMEM ((2 * (G_ASTG + G_BSTG)) * 4)

template <bool RELU>
__global__ __launch_bounds__(256) void gemm_mma(
    const float* __restrict__ A, const float* __restrict__ Bm,
    const float* __restrict__ bias, const float* __restrict__ res,
    float* __restrict__ C, int M, int N, int K) {
    extern __shared__ float sm[];
    float* Bsm = sm + 2 * G_ASTG;
    uint32_t sA = (uint32_t)__cvta_generic_to_shared(sm);
    uint32_t sB = (uint32_t)__cvta_generic_to_shared(Bsm);

    int tid = threadIdx.x;
    int warp = tid >> 5, lane = tid & 31;
    int g = lane >> 2, t = lane & 3;
    int tile = lane >> 3, rl = lane & 7;
    int wm = (warp >> 2) * 64, wn = (warp & 3) * 32;
    int m0 = blockIdx.y * 128, n0 = blockIdx.x * 128;

    float acc[4][4][4] = {};
    int a_rbase = wm + (tile & 1) * 8 + rl;   // + mi*16
    int a_sbase = (tile >> 1);                // + 2*ks

    auto pre = [&](int st, int k0) {
        #pragma unroll
        for (int i = 0; i < 4; i++) {
            int ch = tid + 256 * i;          // 1024 A chunks
            int r = ch >> 3, sg = ch & 7;
            cp16(sA + (uint32_t)(st * G_ASTG + r * 36 + sg * 4) * 4,
                 A + (size_t)(m0 + r) * K + k0 + sg * 4);
        }
        #pragma unroll
        for (int i = 0; i < 4; i++) {
            int ch = tid + 256 * i;          // 1024 B chunks
            int r = ch >> 5, c = (ch & 31) * 4;
            cp16(sB + (uint32_t)(st * G_BSTG + r * 136 + c) * 4,
                 Bm + (size_t)(k0 + r) * N + n0 + c);
        }
        cp_commit();
    };

    pre(0, 0);
    int nk = K >> 5;
    for (int kk = 0; kk < nk; kk++) {
        int st = kk & 1;
        if (kk + 1 < nk) { pre(st ^ 1, (kk + 1) << 5); cp_wait<1>(); }
        else cp_wait<0>();
        __syncthreads();

        const float* bsp = Bsm + st * G_BSTG;
        uint32_t sAs = sA + (uint32_t)(st * G_ASTG) * 4;
        #pragma unroll
        for (int ks = 0; ks < 4; ks++) {
            unsigned af[4][4];
            #pragma unroll
            for (int mi = 0; mi < 4; mi++) {
                ldsm4(af[mi][0], af[mi][1], af[mi][2], af[mi][3],
                      sAs + (uint32_t)((a_rbase + mi * 16) * 36 + (2 * ks + a_sbase) * 4) * 4);
            }
            #pragma unroll
            for (int nj = 0; nj < 4; nj++) {
                unsigned bf[2];
                bf[0] = __float_as_uint(bsp[(ks * 8 + t) * 136 + wn + nj * 8 + g]);
                bf[1] = __float_as_uint(bsp[(ks * 8 + t + 4) * 136 + wn + nj * 8 + g]);
                #pragma unroll
                for (int mi = 0; mi < 4; mi++) mma_tf32(acc[mi][nj], af[mi], bf);
            }
        }
        __syncthreads();
    }

    float4 bv4 = {0.f, 0.f, 0.f, 0.f};
    #pragma unroll
    for (int mi = 0; mi < 4; mi++) {
        #pragma unroll
        for (int nj = 0; nj < 4; nj++) {
            int c = n0 + wn + nj * 8 + 2 * t;
            int r0 = m0 + wm + mi * 16 + g;
            int r1 = r0 + 8;
            float2 o0 = {acc[mi][nj][0], acc[mi][nj][1]};
            float2 o1 = {acc[mi][nj][2], acc[mi][nj][3]};
            if (bias) {
                float2 bv = *(const float2*)(bias + c);
                o0.x += bv.x; o0.y += bv.y; o1.x += bv.x; o1.y += bv.y;
            }
            if (res) {
                float2 ra = *(const float2*)(res + (size_t)r0 * N + c);
                float2 rb = *(const float2*)(res + (size_t)r1 * N + c);
                o0.x += ra.x; o0.y += ra.y; o1.x += rb.x; o1.y += rb.y;
            }
            if (RELU) {
                o0.x = fmaxf(o0.x, 0.f); o0.y = fmaxf(o0.y, 0.f);
                o1.x = fmaxf(o1.x, 0.f); o1.y = fmaxf(o1.y, 0.f);
            }
            *(float2*)(C + (size_t)r0 * N + c) = o0;
            *(float2*)(C + (size_t)r1 * N + c) = o1;
        }
    }
    (void)bv4;
}

// ============================================================
// QKV GEMM: BM=128, BN=64, BK=32, 128 thr = 4 warps (2x2).
// Dynamic smem: 2*(128*36 + 32*72)*4 = 55296 B.
// out layout (b,h,t,d)
// ============================================================
#define Q_ASTG (128 * 36)
#define Q_BSTG (32 * 72)
#define Q_SMEM ((2 * (Q_ASTG + Q_BSTG)) * 4)

__global__ __launch_bounds__(128) void qkv_mma(
    const float* __restrict__ h, const float* __restrict__ wq,
    const float* __restrict__ wk, const float* __restrict__ wv,
    float* __restrict__ q, float* __restrict__ k, float* __restrict__ v) {
    extern __shared__ float sm[];
    float* Bsm = sm + 2 * Q_ASTG;
    uint32_t sA = (uint32_t)__cvta_generic_to_shared(sm);
    uint32_t sB = (uint32_t)__cvta_generic_to_shared(Bsm);

    int which = blockIdx.y / HH, head = blockIdx.y % HH;
    const float* W = (which == 0 ? wq : (which == 1 ? wk : wv)) + (size_t)head * CC * DD;
    float* O = (which == 0 ? q : (which == 1 ? k : v));

    int tid = threadIdx.x;
    int warp = tid >> 5, lane = tid & 31;
    int g = lane >> 2, t = lane & 3;
    int tile = lane >> 3, rl = lane & 7;
    int wm = (warp >> 1) * 64, wn = (warp & 1) * 32;
    int m0 = blockIdx.x * 128;

    float acc[4][4][4] = {};
    int a_rbase = wm + (tile & 1) * 8 + rl;
    int a_sbase = (tile >> 1);

    auto pre = [&](int st, int k0) {
        #pragma unroll
        for (int i = 0; i < 8; i++) {
            int ch = tid + 128 * i;
            int r = ch >> 3, sg = ch & 7;
            cp16(sA + (uint32_t)(st * Q_ASTG + r * 36 + sg * 4) * 4,
                 h + (size_t)(m0 + r) * CC + k0 + sg * 4);
        }
        #pragma unroll
        for (int i = 0; i < 4; i++) {
            int ch = tid + 128 * i;          // 512 B chunks
            int r = ch >> 4, c = (ch & 15) * 4;
            cp16(sB + (uint32_t)(st * Q_BSTG + r * 72 + c) * 4,
                 W + (size_t)(k0 + r) * DD + c);
        }
        cp_commit();
    };

    pre(0, 0);
    for (int kk = 0; kk < CC / 32; kk++) {
        int st = kk & 1;
        if (kk + 1 < CC / 32) { pre(st ^ 1, (kk + 1) << 5); cp_wait<1>(); }
        else cp_wait<0>();
        __syncthreads();

        const float* bsp = Bsm + st * Q_BSTG;
        uint32_t sAs = sA + (uint32_t)(st * Q_ASTG) * 4;
        #pragma unroll
        for (int ks = 0; ks < 4; ks++) {
            unsigned af[4][4];
            #pragma unroll
            for (int mi = 0; mi < 4; mi++) {
                ldsm4(af[mi][0], af[mi][1], af[mi][2], af[mi][3],
                      sAs + (uint32_t)((a_rbase + mi * 16) * 36 + (2 * ks + a_sbase) * 4) * 4);
            }
            #pragma unroll
            for (int nj = 0; nj < 4; nj++) {
                unsigned bf[2];
                bf[0] = __float_as_uint(bsp[(ks * 8 + t) * 72 + wn + nj * 8 + g]);
                bf[1] = __float_as_uint(bsp[(ks * 8 + t + 4) * 72 + wn + nj * 8 + g]);
                #pragma unroll
                for (int mi = 0; mi < 4; mi++) mma_tf32(acc[mi][nj], af[mi], bf);
            }
        }
        __syncthreads();
    }

    #pragma unroll
    for (int mi = 0; mi < 4; mi++) {
        #pragma unroll
        for (int nj = 0; nj < 4; nj++) {
            int c = wn + nj * 8 + 2 * t;
            int m0r = m0 + wm + mi * 16 + g;
            int m1r = m0r + 8;
            int b0 = m0r >> 11, t0i = m0r & (TT - 1);
            int b1 = m1r >> 11, t1i = m1r & (TT - 1);
            float2 o0 = {acc[mi][nj][0], acc[mi][nj][1]};
            float2 o1 = {acc[mi][nj][2], acc[mi][nj][3]};
            *(float2*)(O + (((size_t)(b0 * HH + head) * TT + t0i) << 6) + c) = o0;
            *(float2*)(O + (((size_t)(b1 * HH + head) * TT + t1i) << 6) + c) = o1;
        }
    }
}

// ============================================================
// Flash attention. Br=64, Bc=64, 128 thr (4 warps).
// K via cp.async (key-major), V transposed+swizzled, P aliases Ks.
// All fragments via ldmatrix. Scale 1/8 folded into Q (RNA cvt).
// ============================================================
__global__ __launch_bounds__(128) void attn_mma(
    const float* __restrict__ Q, const float* __restrict__ K,
    const float* __restrict__ V, float* __restrict__ out) {
    __shared__ float Ks[64 * 68];   // K tile (key-major) / aliased P tile (row-major)
    __shared__ float Vt[64 * 68];   // V transposed [d][key], seg-swizzled

    int bh = blockIdx.y;
    int t0 = blockIdx.x * 64;
    const float* Qp = Q + (size_t)bh * TT * DD;
    const float* Kp = K + (size_t)bh * TT * DD;
    const float* Vp = V + (size_t)bh * TT * DD;
    uint32_t sK = (uint32_t)__cvta_generic_to_shared(Ks);
    uint32_t sV = (uint32_t)__cvta_generic_to_shared(Vt);

    int tid = threadIdx.x;
    int warp = tid >> 5, lane = tid & 31;
    int g = lane >> 2, t = lane & 3;
    int tile = lane >> 3, rl = lane & 7;
    int wr = warp * 16;

    // stage Q (scaled, RNA tf32) into Ks, pull A-frags via ldmatrix
    #pragma unroll
    for (int i = 0; i < 8; i++) {
        int idx = tid + 128 * i;
        int r = idx >> 4, c4 = (idx & 15) * 4;
        float4 qv = *(const float4*)(Qp + (size_t)(t0 + r) * DD + c4);
        uint4 u = {f2tf(qv.x * 0.125f), f2tf(qv.y * 0.125f),
                   f2tf(qv.z * 0.125f), f2tf(qv.w * 0.125f)};
        *(uint4*)&Ks[r * 68 + c4] = u;
    }
    __syncthreads();
    unsigned qa[8][4];
    {
        int row = wr + (tile & 1) * 8 + rl;
        #pragma unroll
        for (int ks = 0; ks < 8; ks++)
            ldsm4(qa[ks][0], qa[ks][1], qa[ks][2], qa[ks][3],
                  sK + (uint32_t)(row * 68 + (2 * ks + (tile >> 1)) * 4) * 4);
    }
    __syncthreads();

    float m0r = -1e30f, m1r = -1e30f, l0 = 0.f, l1 = 0.f;
    float oacc[8][4] = {};

    int ntiles = t0 / 64 + 1;
    for (int it = 0; it < ntiles; it++) {
        int s0 = it * 64;
        // K via cp.async (raw fp32 -> tf32 truncation)
        #pragma unroll
        for (int i = 0; i < 8; i++) {
            int ch = tid + 128 * i;
            int r = ch >> 4, sg = ch & 15;
            cp16(sK + (uint32_t)(r * 68 + sg * 4) * 4,
                 Kp + (size_t)(s0 + r) * DD + sg * 4);
        }
        cp_commit();
        // V transpose staging (overlaps K copy)
        #pragma unroll
        for (int i = 0; i < 8; i++) {
            int idx = tid + 128 * i;
            int s = idx >> 4, d4 = (idx & 15) * 4;
            float4 vv = *(const float4*)(Vp + (size_t)(s0 + s) * DD + d4);
            int swz = (d4 >> 2) & 15;
            int pc = 4 * ((s >> 2) ^ swz) + (s & 3);
            Vt[(d4 + 0) * 68 + pc] = vv.x;
            Vt[(d4 + 1) * 68 + pc] = vv.y;
            Vt[(d4 + 2) * 68 + pc] = vv.z;
            Vt[(d4 + 3) * 68 + pc] = vv.w;
        }
        cp_wait<0>();
        __syncthreads();

        // S = Q @ K^T  (K b-frags via ldmatrix, Ks is n-major)
        float sacc[8][4] = {};
        #pragma unroll
        for (int ks = 0; ks < 8; ks++) {
            #pragma unroll
            for (int nj2 = 0; nj2 < 4; nj2++) {
                unsigned r0, r1, r2, r3;
                int row = nj2 * 16 + (tile >> 1) * 8 + rl;
                int seg = 2 * ks + (tile & 1);
                ldsm4(r0, r1, r2, r3, sK + (uint32_t)(row * 68 + seg * 4) * 4);
                unsigned b0[2] = {r0, r1}, b1[2] = {r2, r3};
                mma_tf32(sacc[2 * nj2], qa[ks], b0);
                mma_tf32(sacc[2 * nj2 + 1], qa[ks], b1);
            }
        }
        __syncthreads();   // Ks reads done before P overwrite

        // causal mask (diagonal tile only)
        if (s0 == t0) {
            #pragma unroll
            for (int nj = 0; nj < 8; nj++) {
                int c0 = nj * 8 + 2 * t, c1 = c0 + 1;
                int r0 = wr + g, r1 = r0 + 8;
                if (c0 > r0) sacc[nj][0] = -1e30f;
                if (c1 > r0) sacc[nj][1] = -1e30f;
                if (c0 > r1) sacc[nj][2] = -1e30f;
                if (c1 > r1) sacc[nj][3] = -1e30f;
            }
        }

        // online softmax
        float mt0 = -1e30f, mt1 = -1e30f;
        #pragma unroll
        for (int nj = 0; nj < 8; nj++) {
            mt0 = fmaxf(mt0, fmaxf(sacc[nj][0], sacc[nj][1]));
            mt1 = fmaxf(mt1, fmaxf(sacc[nj][2], sacc[nj][3]));
        }
        #pragma unroll
        for (int o = 1; o <= 2; o <<= 1) {
            mt0 = fmaxf(mt0, __shfl_xor_sync(0xffffffffu, mt0, o));
            mt1 = fmaxf(mt1, __shfl_xor_sync(0xffffffffu, mt1, o));
        }
        float mn0 = fmaxf(m0r, mt0), mn1 = fmaxf(m1r, mt1);
        float sc0 = __expf(m0r - mn0), sc1 = __expf(m1r - mn1);
        float sum0 = 0.f, sum1 = 0.f;
        #pragma unroll
        for (int nj = 0; nj < 8; nj++) {
            float p00 = __expf(sacc[nj][0] - mn0);
            float p01 = __expf(sacc[nj][1] - mn0);
            float p10 = __expf(sacc[nj][2] - mn1);
            float p11 = __expf(sacc[nj][3] - mn1);
            sum0 += p00 + p01; sum1 += p10 + p11;
            int c = nj * 8 + 2 * t;
            Ks[(wr + g) * 68 + c] = p00;     Ks[(wr + g) * 68 + c + 1] = p01;
            Ks[(wr + 8 + g) * 68 + c] = p10; Ks[(wr + 8 + g) * 68 + c + 1] = p11;
        }
        #pragma unroll
        for (int o = 1; o <= 2; o <<= 1) {
            sum0 += __shfl_xor_sync(0xffffffffu, sum0, o);
            sum1 += __shfl_xor_sync(0xffffffffu, sum1, o);
        }
        l0 = l0 * sc0 + sum0;
        l1 = l1 * sc1 + sum1;
        m0r = mn0; m1r = mn1;
        #pragma unroll
        for (int nj = 0; nj < 8; nj++) {
            oacc[nj][0] *= sc0; oacc[nj][1] *= sc0;
            oacc[nj][2] *= sc1; oacc[nj][3] *= sc1;
        }
        __syncthreads();   // P visible to all warps

        // O += P @ V  (P a-frags + V b-frags via ldmatrix)
        #pragma unroll
        for (int j = 0; j < 8; j++) {
            unsigned pa[4];
            {
                int row = wr + (tile & 1) * 8 + rl;
                int seg = 2 * j + (tile >> 1);
                ldsm4(pa[0], pa[1], pa[2], pa[3],
                      sK + (uint32_t)(row * 68 + seg * 4) * 4);
            }
            #pragma unroll
            for (int nj2 = 0; nj2 < 4; nj2++) {
                unsigned r0, r1, r2, r3;
                int row = nj2 * 16 + (tile >> 1) * 8 + rl;
                int lsg = 2 * j + (tile & 1);
                int psg = lsg ^ ((row >> 2) & 15);
                ldsm4(r0, r1, r2, r3, sV + (uint32_t)(row * 68 + psg * 4) * 4);
                unsigned b0[2] = {r0, r1}, b1[2] = {r2, r3};
                mma_tf32(oacc[2 * nj2], pa, b0);
                mma_tf32(oacc[2 * nj2 + 1], pa, b1);
            }
        }
        __syncthreads();   // Ks/Vt consumed before next tile overwrite
    }

    float inv0 = 1.f / l0, inv1 = 1.f / l1;
    int b = bh >> 4, hh = bh & 15;
    int tr0 = t0 + wr + g, tr1 = tr0 + 8;
    #pragma unroll
    for (int nj = 0; nj < 8; nj++) {
        int c = hh * DD + nj * 8 + 2 * t;
        float2 o0 = {oacc[nj][0] * inv0, oacc[nj][1] * inv0};
        float2 o1 = {oacc[nj][2] * inv1, oacc[nj][3] * inv1};
        *(float2*)(out + (size_t)(b * TT + tr0) * CC + c) = o0;
        *(float2*)(out + (size_t)(b * TT + tr1) * CC + c) = o1;
    }
}

// ============================================================
// launch
// ============================================================
extern "C" void kernel_launch(void* const* d_in, const int* in_sizes, int n_in,
                              void* d_out, int out_size) {
    const float* x      = (const float*)d_in[0];
    const float* wq     = (const float*)d_in[1];
    const float* wk     = (const float*)d_in[2];
    const float* wv     = (const float*)d_in[3];
    const float* w_proj = (const float*)d_in[4];
    const float* b_proj = (const float*)d_in[5];
    const float* w1     = (const float*)d_in[6];
    const float* b1     = (const float*)d_in[7];
    const float* w2     = (const float*)d_in[8];
    const float* b2     = (const float*)d_in[9];
    const float* g1     = (const float*)d_in[10];
    const float* be1    = (const float*)d_in[11];
    const float* g2     = (const float*)d_in[12];
    const float* be2    = (const float*)d_in[13];
    float* out = (float*)d_out;

    float *h1, *q, *k, *v, *attn, *x1, *h2, *ff1;
    cudaGetSymbolAddress((void**)&h1, g_h1);
    cudaGetSymbolAddress((void**)&q, g_q);
    cudaGetSymbolAddress((void**)&k, g_k);
    cudaGetSymbolAddress((void**)&v, g_v);
    cudaGetSymbolAddress((void**)&attn, g_attn);
    cudaGetSymbolAddress((void**)&x1, g_x1);
    cudaGetSymbolAddress((void**)&h2, g_h2);
    cudaGetSymbolAddress((void**)&ff1, g_ff1);

    cudaFuncSetAttribute(gemm_mma<false>, cudaFuncAttributeMaxDynamicSharedMemorySize, G_SMEM);
    cudaFuncSetAttribute(gemm_mma<true>,  cudaFuncAttributeMaxDynamicSharedMemorySize, G_SMEM);
    cudaFuncSetAttribute(qkv_mma, cudaFuncAttributeMaxDynamicSharedMemorySize, Q_SMEM);

    // 1. LN1
    ln_kernel<<<MTOT, 256>>>(x, g1, be1, h1);
    // 2. QKV
    qkv_mma<<<dim3(MTOT / 128, 3 * HH), 128, Q_SMEM>>>(h1, wq, wk, wv, q, k, v);
    // 3. attention
    attn_mma<<<dim3(TT / 64, BBATCH * HH), 128>>>(q, k, v, attn);
    // 4. proj + bias + residual -> x1
    gemm_mma<false><<<dim3(CC / 128, MTOT / 128), 256, G_SMEM>>>(attn, w_proj, b_proj, x, x1,
                                                                 MTOT, CC, CC);
    // 5. LN2
    ln_kernel<<<MTOT, 256>>>(x1, g2, be2, h2);
    // 6. FF1 + bias + relu
    gemm_mma<true><<<dim3(FFDIM / 128, MTOT / 128), 256, G_SMEM>>>(h2, w1, b1, nullptr, ff1,
                                                                   MTOT, FFDIM, CC);
    // 7. FF2 + bias + residual -> out
    gemm_mma<false><<<dim3(CC / 128, MTOT / 128), 256, G_SMEM>>>(ff1, w2, b2, x1, out,
                                                                 MTOT, CC, FFDIM);
}